// round 14
// baseline (speedup 1.0000x reference)
#include <cuda_runtime.h>
#include <cstdint>
#include <mma.h>

using namespace nvcuda;

#define DIN   4096
#define DOUT  4096
#define NTOK  8192
#define TIDV  4
#define RNK   8
#define NPE   5
#define NCOLS 35
#define NPAD  48
#define CCOLS 32
#define KSPLIT 8
#define KSLICE (DIN / KSPLIT)   // 512

__device__ float g_MT[NPAD * DIN];
__device__ float g_C[NTOK * CCOLS];
__device__ float g_Zpart[KSPLIT][NTOK][NPAD];
__device__ float g_xt[(size_t)NTOK * DIN];   // tf32-rounded, k-permuted x
__device__ float g_wt[(size_t)DOUT * DIN];   // tf32-rounded, k-permuted W

// ===========================================================================
// helpers
// ===========================================================================
__device__ __forceinline__ uint32_t smem_u32(const void* p) {
    uint32_t r;
    asm("{ .reg .u64 t; cvta.to.shared.u64 t, %1; cvt.u32.u64 %0, t; }" : "=r"(r) : "l"(p));
    return r;
}

__device__ __forceinline__ void cp16(uint32_t dst, const void* src) {
    asm volatile("cp.async.cg.shared.global [%0], [%1], 16;" :: "r"(dst), "l"(src));
}

__device__ __forceinline__ float f2tf_f(float f) {
    uint32_t u;
    asm("cvt.rna.tf32.f32 %0, %1;" : "=r"(u) : "f"(f));
    return __uint_as_float(u);
}

__device__ __forceinline__ void mma_1688(float* d, const uint32_t* a, const uint32_t* b) {
    asm volatile(
        "mma.sync.aligned.m16n8k8.row.col.f32.tf32.tf32.f32 "
        "{%0,%1,%2,%3}, {%4,%5,%6,%7}, {%8,%9}, {%0,%1,%2,%3};"
        : "+f"(d[0]), "+f"(d[1]), "+f"(d[2]), "+f"(d[3])
        : "r"(a[0]), "r"(a[1]), "r"(a[2]), "r"(a[3]), "r"(b[0]), "r"(b[1]));
}

// ===========================================================================
// Kernel 1 (fused preprocess): convert_x + convert_w + pack_mt
// ===========================================================================
#define XB (NTOK * DIN / 4 / 256)          // 8192 blocks
#define WB (DOUT * DIN / 4 / 256)          // 4096 blocks
#define PB ((NPAD * DIN + 255) / 256)      // 768 blocks

__global__ void preprocess_kernel(const float* __restrict__ x,
                                  const float* __restrict__ W,
                                  const float* __restrict__ lora_down,
                                  const float* __restrict__ lora_route) {
    int b = blockIdx.x;
    if (b < XB) {
        int i = b * 256 + threadIdx.x;
        int g = i & 7;
        const float* src = x + (size_t)(i >> 3) * 32 + (g >> 2) * 16 + (g & 3);
        float4 o;
        o.x = f2tf_f(src[0]); o.y = f2tf_f(src[4]);
        o.z = f2tf_f(src[8]); o.w = f2tf_f(src[12]);
        ((float4*)g_xt)[i] = o;
    } else if (b < XB + WB) {
        int i = (b - XB) * 256 + threadIdx.x;
        int g = i & 7;
        const float* src = W + (size_t)(i >> 3) * 32 + (g >> 2) * 16 + (g & 3);
        float4 o;
        o.x = f2tf_f(src[0]); o.y = f2tf_f(src[4]);
        o.z = f2tf_f(src[8]); o.w = f2tf_f(src[12]);
        ((float4*)g_wt)[i] = o;
    } else {
        int idx = (b - XB - WB) * 256 + threadIdx.x;
        if (idx >= NPAD * DIN) return;
        int n = idx / DIN;
        int k = idx - n * DIN;
        float v = 0.f;
        if (n < 3) {
            v = lora_route[(TIDV - 1) * DIN * NPE + k * NPE + n];
        } else if (n < NCOLS) {
            int q = n - 3;
            v = lora_down[(q >> 3) * (DIN * RNK) + k * RNK + (q & 7)];
        }
        g_MT[n * DIN + k] = v;
    }
}

// ===========================================================================
// Kernel 2: split-K prep GEMM (unchanged)
// ===========================================================================
#define P_BM  64
#define P_BK  32
#define P_LDA 40
#define P_LDZ 48

__global__ __launch_bounds__(128) void prep_split_kernel(const float* __restrict__ x) {
    __shared__ float As[P_BM][P_LDA];
    __shared__ float Bs[NPAD][P_LDA];
    __shared__ float Zs[P_BM][P_LDZ];

    const int tid  = threadIdx.x;
    const int warp = tid >> 5;
    const int m0   = blockIdx.x * P_BM;
    const int ks   = blockIdx.y;
    const int row  = tid >> 1;
    const int half = tid & 1;

    wmma::fragment<wmma::accumulator, 16, 16, 8, float> acc[3];
#pragma unroll
    for (int j = 0; j < 3; j++) wmma::fill_fragment(acc[j], 0.f);

    for (int c = 0; c < KSLICE / P_BK; c++) {
        const int k0 = ks * KSLICE + c * P_BK;
#pragma unroll
        for (int v = 0; v < 4; v++) {
            float4 t = *(const float4*)(x + (size_t)(m0 + row) * DIN + k0 + half * 16 + v * 4);
            *(float4*)(&As[row][half * 16 + v * 4]) = t;
        }
        for (int idx = tid; idx < NPAD * 8; idx += 128) {
            int n = idx >> 3, q = idx & 7;
            float4 t = *(const float4*)(g_MT + n * DIN + k0 + q * 4);
            *(float4*)(&Bs[n][q * 4]) = t;
        }
        __syncthreads();

#pragma unroll
        for (int kss = 0; kss < 4; kss++) {
            const int k = kss * 8;
            wmma::fragment<wmma::matrix_a, 16, 16, 8, wmma::precision::tf32, wmma::row_major> a;
            wmma::load_matrix_sync(a, &As[warp * 16][k], P_LDA);
#pragma unroll
            for (int e = 0; e < a.num_elements; e++) a.x[e] = wmma::__float_to_tf32(a.x[e]);
#pragma unroll
            for (int j = 0; j < 3; j++) {
                wmma::fragment<wmma::matrix_b, 16, 16, 8, wmma::precision::tf32, wmma::col_major> b;
                wmma::load_matrix_sync(b, &Bs[j * 16][k], P_LDA);
#pragma unroll
                for (int e = 0; e < b.num_elements; e++) b.x[e] = wmma::__float_to_tf32(b.x[e]);
                wmma::mma_sync(acc[j], a, b, acc[j]);
            }
        }
        __syncthreads();
    }

#pragma unroll
    for (int j = 0; j < 3; j++)
        wmma::store_matrix_sync(&Zs[warp * 16][j * 16], acc[j], P_LDZ, wmma::mem_row_major);
    __syncthreads();

    for (int idx = tid; idx < P_BM * NPAD; idx += 128) {
        int m = idx / NPAD, col = idx % NPAD;
        g_Zpart[ks][m0 + m][col] = Zs[m][col];
    }
}

// ===========================================================================
// Kernel 3: gating (unchanged)
// ===========================================================================
__global__ void gating_kernel() {
    int t = blockIdx.x * blockDim.x + threadIdx.x;
    if (t >= NTOK) return;
    float z[36];
#pragma unroll
    for (int j = 0; j < 9; j++) {
        float4 v = *(const float4*)(&g_Zpart[0][t][j * 4]);
        z[j * 4 + 0] = v.x; z[j * 4 + 1] = v.y; z[j * 4 + 2] = v.z; z[j * 4 + 3] = v.w;
    }
#pragma unroll
    for (int s = 1; s < KSPLIT; s++) {
#pragma unroll
        for (int j = 0; j < 9; j++) {
            float4 v = *(const float4*)(&g_Zpart[s][t][j * 4]);
            z[j * 4 + 0] += v.x; z[j * 4 + 1] += v.y; z[j * 4 + 2] += v.z; z[j * 4 + 3] += v.w;
        }
    }
    float mx = fmaxf(z[0], fmaxf(z[1], z[2]));
    float e0 = expf(z[0] - mx), e1 = expf(z[1] - mx), e2 = expf(z[2] - mx);
    float inv = 1.f / (e0 + e1 + e2);
    float om[3] = {e0 * inv, e1 * inv, e2 * inv};
#pragma unroll
    for (int q = 0; q < CCOLS; q++) {
        float w = (q < 24) ? om[q >> 3] : 1.f;
        int pos = 16 * (q >> 4) + 4 * (q & 3) + ((q >> 2) & 3);
        g_C[(size_t)t * CCOLS + pos] = f2tf_f(z[3 + q] * w);
    }
}

// ===========================================================================
// Kernel 4: main GEMM — 128x128 tile, 256 threads (8 warps 2x4, warp tile
//   64x32, acc=64 regs), __launch_bounds__(256,2) -> 16 warps/SM for
//   latency hiding on the tensor pipe. Same smem layout / 3-stage cp.async.
// ===========================================================================
#define BM 128
#define BN 128
#define BKF 32
#define NCHUNK (DIN / BKF)        // 128
#define A_FL (BM * BKF)           // 4096 floats
#define B_FL (BN * BKF)           // 4096 floats
#define STG_FL (A_FL + B_FL)      // 8192 floats
#define A_BYTES (A_FL * 4)        // 16384
#define STG_BYTES (STG_FL * 4)    // 32768
#define SMEM_BYTES (3 * STG_BYTES) // 98304

// one j2 half of a 32-wide K chunk; warp tile 64x32 (4 mi x 4 nj)
__device__ __forceinline__ void compute_half(
    const float* __restrict__ As, const float* __restrict__ Bs,
    const int* ra0, const int* ra1, const int* rbv,
    int offj, float acc[4][4][4])
{
    uint4 A0[4], A1[4], B[4];
#pragma unroll
    for (int mi = 0; mi < 4; mi++) {
        A0[mi] = *(const uint4*)(As + ra0[mi] + offj);
        A1[mi] = *(const uint4*)(As + ra1[mi] + offj);
    }
#pragma unroll
    for (int nj = 0; nj < 4; nj++)
        B[nj] = *(const uint4*)(Bs + rbv[nj] + offj);

#pragma unroll
    for (int nj = 0; nj < 4; nj++) {
        uint32_t blo[2] = {B[nj].x, B[nj].y};
#pragma unroll
        for (int mi = 0; mi < 4; mi++) {
            uint32_t alo[4] = {A0[mi].x, A1[mi].x, A0[mi].y, A1[mi].y};
            mma_1688(acc[mi][nj], alo, blo);
        }
    }
#pragma unroll
    for (int nj = 0; nj < 4; nj++) {
        uint32_t bhi[2] = {B[nj].z, B[nj].w};
#pragma unroll
        for (int mi = 0; mi < 4; mi++) {
            uint32_t ahi[4] = {A0[mi].z, A1[mi].z, A0[mi].w, A1[mi].w};
            mma_1688(acc[mi][nj], ahi, bhi);
        }
    }
}

__global__ __launch_bounds__(256, 2) void main_mma_kernel(
    const float* __restrict__ lora_up,
    float* __restrict__ out)
{
    extern __shared__ float sm[];
    const uint32_t smb = smem_u32(sm);

    const int tid  = threadIdx.x;
    const int warp = tid >> 5;
    const int lane = tid & 31;
    const int qid  = lane >> 2;
    const int tid4 = lane & 3;
    const int wm   = warp >> 2;   // 0..1 (64 rows)
    const int wn   = warp & 3;    // 0..3 (32 cols)
    const int m0   = blockIdx.y * BM;
    const int n0   = blockIdx.x * BN;

    // fragment row bases; rows have (r&7)==qid, parity = qid&1
    int ra0[4], ra1[4], rbv[4], off[2];
#pragma unroll
    for (int mi = 0; mi < 4; mi++) {
        int r = wm * 64 + mi * 16 + qid;
        ra0[mi] = r * 32;
        ra1[mi] = ra0[mi] + 8 * 32;
    }
#pragma unroll
    for (int nj = 0; nj < 4; nj++) {
        int r = wn * 32 + nj * 8 + qid;
        rbv[nj] = r * 32;
    }
    const int psw = (qid & 1) << 2;
#pragma unroll
    for (int j2 = 0; j2 < 2; j2++) off[j2] = ((4 * j2 + tid4) ^ psw) << 2;

    // cp.async: 256 threads; thread handles rows r0 + v*32 (v<4), block blk
    const int r0  = tid >> 3;     // 0..31
    const int blk = tid & 7;
    const uint32_t aD = (uint32_t)((r0 * 32 + ((blk ^ ((r0 & 1) << 2)) << 2)) * 4);
    const float* aS = g_xt + (size_t)(m0 + r0) * DIN + blk * 4;
    const float* bS = g_wt + (size_t)(n0 + r0) * DIN + blk * 4;

    float acc[4][4][4];
#pragma unroll
    for (int mi = 0; mi < 4; mi++)
#pragma unroll
        for (int nj = 0; nj < 4; nj++)
#pragma unroll
            for (int e = 0; e < 4; e++) acc[mi][nj][e] = 0.f;

    // prologue: chunks 0,1 -> stages 0,1 (rows stride 32 -> 4KB smem stride)
#pragma unroll
    for (int p = 0; p < 2; p++) {
        const uint32_t ab = smb + p * STG_BYTES;
#pragma unroll
        for (int v = 0; v < 4; v++) cp16(ab + aD + v * 4096, aS + (size_t)v * 32 * DIN + p * 32);
#pragma unroll
        for (int v = 0; v < 4; v++) cp16(ab + A_BYTES + aD + v * 4096, bS + (size_t)v * 32 * DIN + p * 32);
        asm volatile("cp.async.commit_group;" ::: "memory");
    }

    int stage = 0;
#pragma unroll 1
    for (int c = 0; c < NCHUNK; c++) {
        if (c == NCHUNK - 1) asm volatile("cp.async.wait_group 0;" ::: "memory");
        else                 asm volatile("cp.async.wait_group 1;" ::: "memory");
        __syncthreads();

        if (c + 2 < NCHUNK) {
            int ns = stage + 2; if (ns >= 3) ns -= 3;
            const uint32_t ab = smb + ns * STG_BYTES;
            const int ko = (c + 2) * 32;
#pragma unroll
            for (int v = 0; v < 4; v++) cp16(ab + aD + v * 4096, aS + (size_t)v * 32 * DIN + ko);
#pragma unroll
            for (int v = 0; v < 4; v++) cp16(ab + A_BYTES + aD + v * 4096, bS + (size_t)v * 32 * DIN + ko);
            asm volatile("cp.async.commit_group;" ::: "memory");
        }

        const float* As = sm + stage * STG_FL;
        const float* Bs = As + A_FL;
        compute_half(As, Bs, ra0, ra1, rbv, off[0], acc);
        compute_half(As, Bs, ra0, ra1, rbv, off[1], acc);

        stage++; if (stage == 3) stage = 0;
    }

    // ---- LoRA delta chunk: A = gated C (tf32 + permuted), B = U^T
    __syncthreads();
    {
#pragma unroll
        for (int v = 0; v < 4; v++) {
            float4 t = *(const float4*)(g_C + (size_t)(m0 + r0 + v * 32) * CCOLS + blk * 4);
            *(float4*)((char*)sm + aD + v * 4096) = t;
        }
        if (tid < BN) {
            const int n = tid;
            const int nsw = (n & 1) << 2;
#pragma unroll
            for (int k = 0; k < 32; k++) {
                int g = 4 * (k >> 4) + (k & 3);
                int u = (k >> 2) & 3;
                sm[A_FL + n * 32 + ((g ^ nsw) << 2) + u] =
                    f2tf_f(lora_up[(size_t)k * DOUT + n0 + n]);
            }
        }
    }
    __syncthreads();
    compute_half(sm, sm + A_FL, ra0, ra1, rbv, off[0], acc);
    compute_half(sm, sm + A_FL, ra0, ra1, rbv, off[1], acc);

    // ---- epilogue
#pragma unroll
    for (int mi = 0; mi < 4; mi++) {
        const int row = m0 + wm * 64 + mi * 16 + qid;
#pragma unroll
        for (int nj = 0; nj < 4; nj++) {
            const int col = n0 + wn * 32 + nj * 8 + tid4 * 2;
            float2 v0 = make_float2(acc[mi][nj][0], acc[mi][nj][1]);
            float2 v1 = make_float2(acc[mi][nj][2], acc[mi][nj][3]);
            *(float2*)(out + (size_t)row * DOUT + col) = v0;
            *(float2*)(out + (size_t)(row + 8) * DOUT + col) = v1;
        }
    }
}

// ===========================================================================
// Launch: 4 launches, single stream; main GEMM in slot 4 (profiled).
// ===========================================================================
extern "C" void kernel_launch(void* const* d_in, const int* in_sizes, int n_in,
                              void* d_out, int out_size) {
    const float* x          = (const float*)d_in[0];
    const float* W          = (const float*)d_in[1];
    const float* lora_down  = (const float*)d_in[2];
    const float* lora_up    = (const float*)d_in[3];
    const float* lora_route = (const float*)d_in[4];
    float* out = (float*)d_out;

    cudaFuncSetAttribute(main_mma_kernel, cudaFuncAttributeMaxDynamicSharedMemorySize,
                         SMEM_BYTES);

    preprocess_kernel<<<XB + WB + PB, 256>>>(x, W, lora_down, lora_route);
    {
        dim3 pgrid(NTOK / P_BM, KSPLIT);   // (128, 8)
        prep_split_kernel<<<pgrid, 128>>>(x);
    }
    gating_kernel<<<NTOK / 256, 256>>>();
    {
        dim3 grid(DOUT / BN, NTOK / BM);   // (32, 64)
        main_mma_kernel<<<grid, 256, SMEM_BYTES>>>(lora_up, out);
    }
}

// round 15
// speedup vs baseline: 1.0375x; 1.0375x over previous
#include <cuda_runtime.h>
#include <cstdint>
#include <mma.h>

using namespace nvcuda;

#define DIN   4096
#define DOUT  4096
#define NTOK  8192
#define TIDV  4
#define RNK   8
#define NPE   5
#define NCOLS 35
#define NPAD  48
#define CCOLS 32
#define KSPLIT 8
#define KSLICE (DIN / KSPLIT)   // 512

__device__ float g_MT[NPAD * DIN];           // k-permuted (matches g_xt)
__device__ float g_C[NTOK * CCOLS];
__device__ float g_Zpart[KSPLIT][NTOK][NPAD];
__device__ float g_xt[(size_t)NTOK * DIN];   // tf32-rounded, k-permuted x
__device__ float g_wt[(size_t)DOUT * DIN];   // tf32-rounded, k-permuted W

// ===========================================================================
// helpers
// ===========================================================================
__device__ __forceinline__ uint32_t smem_u32(const void* p) {
    uint32_t r;
    asm("{ .reg .u64 t; cvta.to.shared.u64 t, %1; cvt.u32.u64 %0, t; }" : "=r"(r) : "l"(p));
    return r;
}

__device__ __forceinline__ void cp16(uint32_t dst, const void* src) {
    asm volatile("cp.async.cg.shared.global [%0], [%1], 16;" :: "r"(dst), "l"(src));
}

__device__ __forceinline__ float f2tf_f(float f) {
    uint32_t u;
    asm("cvt.rna.tf32.f32 %0, %1;" : "=r"(u) : "f"(f));
    return __uint_as_float(u);
}

__device__ __forceinline__ void mma_1688(float* d, const uint32_t* a, const uint32_t* b) {
    asm volatile(
        "mma.sync.aligned.m16n8k8.row.col.f32.tf32.tf32.f32 "
        "{%0,%1,%2,%3}, {%4,%5,%6,%7}, {%8,%9}, {%0,%1,%2,%3};"
        : "+f"(d[0]), "+f"(d[1]), "+f"(d[2]), "+f"(d[3])
        : "r"(a[0]), "r"(a[1]), "r"(a[2]), "r"(a[3]), "r"(b[0]), "r"(b[1]));
}

// permutation used by preprocess within each 32-float chunk:
// position p holds logical k q with p = 16*(q>>4) + 4*(q&3) + ((q>>2)&3)
__device__ __forceinline__ int kperm(int q) {
    return 16 * (q >> 4) + 4 * (q & 3) + ((q >> 2) & 3);
}

// ===========================================================================
// Kernel 1 (fused preprocess): convert_x + convert_w + pack_mt (permuted)
// ===========================================================================
#define XB (NTOK * DIN / 4 / 256)          // 8192 blocks
#define WB (DOUT * DIN / 4 / 256)          // 4096 blocks
#define PB ((NPAD * DIN + 255) / 256)      // 768 blocks

__global__ void preprocess_kernel(const float* __restrict__ x,
                                  const float* __restrict__ W,
                                  const float* __restrict__ lora_down,
                                  const float* __restrict__ lora_route) {
    int b = blockIdx.x;
    if (b < XB) {
        int i = b * 256 + threadIdx.x;
        int g = i & 7;
        const float* src = x + (size_t)(i >> 3) * 32 + (g >> 2) * 16 + (g & 3);
        float4 o;
        o.x = f2tf_f(src[0]); o.y = f2tf_f(src[4]);
        o.z = f2tf_f(src[8]); o.w = f2tf_f(src[12]);
        ((float4*)g_xt)[i] = o;
    } else if (b < XB + WB) {
        int i = (b - XB) * 256 + threadIdx.x;
        int g = i & 7;
        const float* src = W + (size_t)(i >> 3) * 32 + (g >> 2) * 16 + (g & 3);
        float4 o;
        o.x = f2tf_f(src[0]); o.y = f2tf_f(src[4]);
        o.z = f2tf_f(src[8]); o.w = f2tf_f(src[12]);
        ((float4*)g_wt)[i] = o;
    } else {
        int idx = (b - XB - WB) * 256 + threadIdx.x;
        if (idx >= NPAD * DIN) return;
        int n = idx / DIN;
        int k = idx - n * DIN;            // logical k
        float v = 0.f;
        if (n < 3) {
            v = lora_route[(TIDV - 1) * DIN * NPE + k * NPE + n];
        } else if (n < NCOLS) {
            int q = n - 3;
            v = lora_down[(q >> 3) * (DIN * RNK) + k * RNK + (q & 7)];
        }
        // store tf32-rounded at permuted position (matches g_xt layout)
        g_MT[n * DIN + (k & ~31) + kperm(k & 31)] = f2tf_f(v);
    }
}

// ===========================================================================
// Kernel 2: split-K prep GEMM — reads g_xt / permuted g_MT (both already
//   tf32-rounded and identically k-permuted -> NO cvt loops needed; every
//   K=8 wmma window sums a matched set of logical k's)
// ===========================================================================
#define P_BM  64
#define P_BK  32
#define P_LDA 40
#define P_LDZ 48

__global__ __launch_bounds__(128) void prep_split_kernel() {
    __shared__ float As[P_BM][P_LDA];
    __shared__ float Bs[NPAD][P_LDA];
    __shared__ float Zs[P_BM][P_LDZ];

    const int tid  = threadIdx.x;
    const int warp = tid >> 5;
    const int m0   = blockIdx.x * P_BM;
    const int ks   = blockIdx.y;
    const int row  = tid >> 1;
    const int half = tid & 1;

    wmma::fragment<wmma::accumulator, 16, 16, 8, float> acc[3];
#pragma unroll
    for (int j = 0; j < 3; j++) wmma::fill_fragment(acc[j], 0.f);

    for (int c = 0; c < KSLICE / P_BK; c++) {
        const int k0 = ks * KSLICE + c * P_BK;
#pragma unroll
        for (int v = 0; v < 4; v++) {
            float4 t = *(const float4*)(g_xt + (size_t)(m0 + row) * DIN + k0 + half * 16 + v * 4);
            *(float4*)(&As[row][half * 16 + v * 4]) = t;
        }
        for (int idx = tid; idx < NPAD * 8; idx += 128) {
            int n = idx >> 3, q = idx & 7;
            float4 t = *(const float4*)(g_MT + n * DIN + k0 + q * 4);
            *(float4*)(&Bs[n][q * 4]) = t;
        }
        __syncthreads();

#pragma unroll
        for (int kss = 0; kss < 4; kss++) {
            const int k = kss * 8;
            wmma::fragment<wmma::matrix_a, 16, 16, 8, wmma::precision::tf32, wmma::row_major> a;
            wmma::load_matrix_sync(a, &As[warp * 16][k], P_LDA);
#pragma unroll
            for (int j = 0; j < 3; j++) {
                wmma::fragment<wmma::matrix_b, 16, 16, 8, wmma::precision::tf32, wmma::col_major> b;
                wmma::load_matrix_sync(b, &Bs[j * 16][k], P_LDA);
                wmma::mma_sync(acc[j], a, b, acc[j]);
            }
        }
        __syncthreads();
    }

#pragma unroll
    for (int j = 0; j < 3; j++)
        wmma::store_matrix_sync(&Zs[warp * 16][j * 16], acc[j], P_LDZ, wmma::mem_row_major);
    __syncthreads();

    for (int idx = tid; idx < P_BM * NPAD; idx += 128) {
        int m = idx / NPAD, col = idx % NPAD;
        g_Zpart[ks][m0 + m][col] = Zs[m][col];
    }
}

// ===========================================================================
// Kernel 3: gating (unchanged)
// ===========================================================================
__global__ void gating_kernel() {
    int t = blockIdx.x * blockDim.x + threadIdx.x;
    if (t >= NTOK) return;
    float z[36];
#pragma unroll
    for (int j = 0; j < 9; j++) {
        float4 v = *(const float4*)(&g_Zpart[0][t][j * 4]);
        z[j * 4 + 0] = v.x; z[j * 4 + 1] = v.y; z[j * 4 + 2] = v.z; z[j * 4 + 3] = v.w;
    }
#pragma unroll
    for (int s = 1; s < KSPLIT; s++) {
#pragma unroll
        for (int j = 0; j < 9; j++) {
            float4 v = *(const float4*)(&g_Zpart[s][t][j * 4]);
            z[j * 4 + 0] += v.x; z[j * 4 + 1] += v.y; z[j * 4 + 2] += v.z; z[j * 4 + 3] += v.w;
        }
    }
    float mx = fmaxf(z[0], fmaxf(z[1], z[2]));
    float e0 = expf(z[0] - mx), e1 = expf(z[1] - mx), e2 = expf(z[2] - mx);
    float inv = 1.f / (e0 + e1 + e2);
    float om[3] = {e0 * inv, e1 * inv, e2 * inv};
#pragma unroll
    for (int q = 0; q < CCOLS; q++) {
        float w = (q < 24) ? om[q >> 3] : 1.f;
        int pos = 16 * (q >> 4) + 4 * (q & 3) + ((q >> 2) & 3);
        g_C[(size_t)t * CCOLS + pos] = f2tf_f(z[3 + q] * w);
    }
}

// ===========================================================================
// Kernel 4: main GEMM — EXACT round-11 (1487us) configuration: 128x128 tile,
//   128 threads (4 warps 2x2, warp tile 64x64), 2 CTAs/SM, 3-stage cp.async
//   burst before compute_chunk, 2D grid n-fastest. FROZEN.
// ===========================================================================
#define BM 128
#define BN 128
#define BKF 32
#define NCHUNK (DIN / BKF)        // 128
#define A_FL (BM * BKF)           // 4096 floats
#define B_FL (BN * BKF)           // 4096 floats
#define STG_FL (A_FL + B_FL)      // 8192 floats
#define A_BYTES (A_FL * 4)        // 16384
#define STG_BYTES (STG_FL * 4)    // 32768
#define SMEM_BYTES (3 * STG_BYTES) // 98304

__device__ __forceinline__ void compute_chunk(
    const float* __restrict__ As, const float* __restrict__ Bs,
    const int* ra0, const int* ra1, const int* rbv,
    const int* off, float acc[4][8][4])
{
#pragma unroll
    for (int j2 = 0; j2 < 2; j2++) {
        uint4 A0[4], A1[4], B[8];
#pragma unroll
        for (int mi = 0; mi < 4; mi++) {
            A0[mi] = *(const uint4*)(As + ra0[mi] + off[j2]);
            A1[mi] = *(const uint4*)(As + ra1[mi] + off[j2]);
        }
#pragma unroll
        for (int nj = 0; nj < 8; nj++)
            B[nj] = *(const uint4*)(Bs + rbv[nj] + off[j2]);

#pragma unroll
        for (int nj = 0; nj < 8; nj++) {
            uint32_t blo[2] = {B[nj].x, B[nj].y};
#pragma unroll
            for (int mi = 0; mi < 4; mi++) {
                uint32_t alo[4] = {A0[mi].x, A1[mi].x, A0[mi].y, A1[mi].y};
                mma_1688(acc[mi][nj], alo, blo);
            }
        }
#pragma unroll
        for (int nj = 0; nj < 8; nj++) {
            uint32_t bhi[2] = {B[nj].z, B[nj].w};
#pragma unroll
            for (int mi = 0; mi < 4; mi++) {
                uint32_t ahi[4] = {A0[mi].z, A1[mi].z, A0[mi].w, A1[mi].w};
                mma_1688(acc[mi][nj], ahi, bhi);
            }
        }
    }
}

__global__ __launch_bounds__(128, 2) void main_mma_kernel(
    const float* __restrict__ lora_up,
    float* __restrict__ out)
{
    extern __shared__ float sm[];
    const uint32_t smb = smem_u32(sm);

    const int tid  = threadIdx.x;
    const int warp = tid >> 5;
    const int lane = tid & 31;
    const int qid  = lane >> 2;
    const int tid4 = lane & 3;
    const int wm   = warp >> 1;   // 0..1
    const int wn   = warp & 1;    // 0..1
    const int m0   = blockIdx.y * BM;
    const int n0   = blockIdx.x * BN;

    int ra0[4], ra1[4], rbv[8], off[2];
#pragma unroll
    for (int mi = 0; mi < 4; mi++) {
        int r = wm * 64 + mi * 16 + qid;
        ra0[mi] = r * 32;
        ra1[mi] = ra0[mi] + 8 * 32;
    }
#pragma unroll
    for (int nj = 0; nj < 8; nj++) {
        int r = wn * 64 + nj * 8 + qid;
        rbv[nj] = r * 32;
    }
    const int psw = (qid & 1) << 2;
#pragma unroll
    for (int j2 = 0; j2 < 2; j2++) off[j2] = ((4 * j2 + tid4) ^ psw) << 2;

    const int r0  = tid >> 3;     // 0..15
    const int blk = tid & 7;
    const uint32_t aD = (uint32_t)((r0 * 32 + ((blk ^ ((r0 & 1) << 2)) << 2)) * 4);
    const float* aS = g_xt + (size_t)(m0 + r0) * DIN + blk * 4;
    const float* bS = g_wt + (size_t)(n0 + r0) * DIN + blk * 4;

    float acc[4][8][4];
#pragma unroll
    for (int mi = 0; mi < 4; mi++)
#pragma unroll
        for (int nj = 0; nj < 8; nj++)
#pragma unroll
            for (int e = 0; e < 4; e++) acc[mi][nj][e] = 0.f;

#pragma unroll
    for (int p = 0; p < 2; p++) {
        const uint32_t ab = smb + p * STG_BYTES;
#pragma unroll
        for (int v = 0; v < 8; v++) cp16(ab + aD + v * 2048, aS + (size_t)v * 16 * DIN + p * 32);
#pragma unroll
        for (int v = 0; v < 8; v++) cp16(ab + A_BYTES + aD + v * 2048, bS + (size_t)v * 16 * DIN + p * 32);
        asm volatile("cp.async.commit_group;" ::: "memory");
    }

    int stage = 0;
#pragma unroll 1
    for (int c = 0; c < NCHUNK; c++) {
        if (c == NCHUNK - 1) asm volatile("cp.async.wait_group 0;" ::: "memory");
        else                 asm volatile("cp.async.wait_group 1;" ::: "memory");
        __syncthreads();

        if (c + 2 < NCHUNK) {
            int ns = stage + 2; if (ns >= 3) ns -= 3;
            const uint32_t ab = smb + ns * STG_BYTES;
            const int ko = (c + 2) * 32;
#pragma unroll
            for (int v = 0; v < 8; v++) cp16(ab + aD + v * 2048, aS + (size_t)v * 16 * DIN + ko);
#pragma unroll
            for (int v = 0; v < 8; v++) cp16(ab + A_BYTES + aD + v * 2048, bS + (size_t)v * 16 * DIN + ko);
            asm volatile("cp.async.commit_group;" ::: "memory");
        }

        compute_chunk(sm + stage * STG_FL, sm + stage * STG_FL + A_FL,
                      ra0, ra1, rbv, off, acc);

        stage++; if (stage == 3) stage = 0;
    }

    // ---- LoRA delta chunk
    __syncthreads();
    {
#pragma unroll
        for (int v = 0; v < 8; v++) {
            float4 t = *(const float4*)(g_C + (size_t)(m0 + r0 + v * 16) * CCOLS + blk * 4);
            *(float4*)((char*)sm + aD + v * 2048) = t;
        }
        const int n = tid;
        const int nsw = (n & 1) << 2;
#pragma unroll
        for (int k = 0; k < 32; k++) {
            int g = 4 * (k >> 4) + (k & 3);
            int u = (k >> 2) & 3;
            sm[A_FL + n * 32 + ((g ^ nsw) << 2) + u] =
                f2tf_f(lora_up[(size_t)k * DOUT + n0 + n]);
        }
    }
    __syncthreads();
    compute_chunk(sm, sm + A_FL, ra0, ra1, rbv, off, acc);

    // ---- epilogue
#pragma unroll
    for (int mi = 0; mi < 4; mi++) {
        const int row = m0 + wm * 64 + mi * 16 + qid;
#pragma unroll
        for (int nj = 0; nj < 8; nj++) {
            const int col = n0 + wn * 64 + nj * 8 + tid4 * 2;
            float2 v0 = make_float2(acc[mi][nj][0], acc[mi][nj][1]);
            float2 v1 = make_float2(acc[mi][nj][2], acc[mi][nj][3]);
            *(float2*)(out + (size_t)row * DOUT + col) = v0;
            *(float2*)(out + (size_t)(row + 8) * DOUT + col) = v1;
        }
    }
}

// ===========================================================================
// Launch: 4 launches, single stream; main GEMM in slot 4 (profiled).
// ===========================================================================
extern "C" void kernel_launch(void* const* d_in, const int* in_sizes, int n_in,
                              void* d_out, int out_size) {
    const float* x          = (const float*)d_in[0];
    const float* W          = (const float*)d_in[1];
    const float* lora_down  = (const float*)d_in[2];
    const float* lora_up    = (const float*)d_in[3];
    const float* lora_route = (const float*)d_in[4];
    float* out = (float*)d_out;

    cudaFuncSetAttribute(main_mma_kernel, cudaFuncAttributeMaxDynamicSharedMemorySize,
                         SMEM_BYTES);

    preprocess_kernel<<<XB + WB + PB, 256>>>(x, W, lora_down, lora_route);
    {
        dim3 pgrid(NTOK / P_BM, KSPLIT);   // (128, 8)
        prep_split_kernel<<<pgrid, 128>>>();
    }
    gating_kernel<<<NTOK / 256, 256>>>();
    {
        dim3 grid(DOUT / BN, NTOK / BM);   // (32, 64)
        main_mma_kernel<<<grid, 128, SMEM_BYTES>>>(lora_up, out);
    }
}

// round 16
// speedup vs baseline: 1.0771x; 1.0382x over previous
#include <cuda_runtime.h>
#include <cstdint>
#include <mma.h>

using namespace nvcuda;

#define DIN   4096
#define DOUT  4096
#define NTOK  8192
#define TIDV  4
#define RNK   8
#define NPE   5
#define NCOLS 35
#define NPAD  48
#define CCOLS 32
#define KSPLIT 8
#define KSLICE (DIN / KSPLIT)   // 512

__device__ float g_MT[NPAD * DIN];           // natural k-order
__device__ float g_C[NTOK * CCOLS];          // natural k-order
__device__ float g_Zpart[KSPLIT][NTOK][NPAD];

// ===========================================================================
// helpers
// ===========================================================================
__device__ __forceinline__ uint32_t smem_u32(const void* p) {
    uint32_t r;
    asm("{ .reg .u64 t; cvta.to.shared.u64 t, %1; cvt.u32.u64 %0, t; }" : "=r"(r) : "l"(p));
    return r;
}

__device__ __forceinline__ void cp16(uint32_t dst, const void* src) {
    asm volatile("cp.async.cg.shared.global [%0], [%1], 16;" :: "r"(dst), "l"(src));
}

// raw fp32 fed to mma.tf32: HW ignores low 13 mantissa bits (truncation)
__device__ __forceinline__ void mma_1688(float* d, const uint32_t* a, const uint32_t* b) {
    asm volatile(
        "mma.sync.aligned.m16n8k8.row.col.f32.tf32.tf32.f32 "
        "{%0,%1,%2,%3}, {%4,%5,%6,%7}, {%8,%9}, {%0,%1,%2,%3};"
        : "+f"(d[0]), "+f"(d[1]), "+f"(d[2]), "+f"(d[3])
        : "r"(a[0]), "r"(a[1]), "r"(a[2]), "r"(a[3]), "r"(b[0]), "r"(b[1]));
}

// ===========================================================================
// Kernel 1: pack M^T (natural k-order, raw values)
// ===========================================================================
__global__ void pack_mt_kernel(const float* __restrict__ lora_down,
                               const float* __restrict__ lora_route) {
    int idx = blockIdx.x * blockDim.x + threadIdx.x;
    if (idx >= NPAD * DIN) return;
    int n = idx / DIN;
    int k = idx - n * DIN;
    float v = 0.f;
    if (n < 3) {
        v = lora_route[(TIDV - 1) * DIN * NPE + k * NPE + n];
    } else if (n < NCOLS) {
        int q = n - 3;
        v = lora_down[(q >> 3) * (DIN * RNK) + k * RNK + (q & 7)];
    }
    g_MT[n * DIN + k] = v;
}

// ===========================================================================
// Kernel 2: split-K prep GEMM — raw x and g_MT, no CVT (HW truncation on
//   both operands; layouts identical on both sides -> consistent k-mapping)
// ===========================================================================
#define P_BM  64
#define P_BK  32
#define P_LDA 40
#define P_LDZ 48

__global__ __launch_bounds__(128) void prep_split_kernel(const float* __restrict__ x) {
    __shared__ float As[P_BM][P_LDA];
    __shared__ float Bs[NPAD][P_LDA];
    __shared__ float Zs[P_BM][P_LDZ];

    const int tid  = threadIdx.x;
    const int warp = tid >> 5;
    const int m0   = blockIdx.x * P_BM;
    const int ks   = blockIdx.y;
    const int row  = tid >> 1;
    const int half = tid & 1;

    wmma::fragment<wmma::accumulator, 16, 16, 8, float> acc[3];
#pragma unroll
    for (int j = 0; j < 3; j++) wmma::fill_fragment(acc[j], 0.f);

    for (int c = 0; c < KSLICE / P_BK; c++) {
        const int k0 = ks * KSLICE + c * P_BK;
#pragma unroll
        for (int v = 0; v < 4; v++) {
            float4 t = *(const float4*)(x + (size_t)(m0 + row) * DIN + k0 + half * 16 + v * 4);
            *(float4*)(&As[row][half * 16 + v * 4]) = t;
        }
        for (int idx = tid; idx < NPAD * 8; idx += 128) {
            int n = idx >> 3, q = idx & 7;
            float4 t = *(const float4*)(g_MT + n * DIN + k0 + q * 4);
            *(float4*)(&Bs[n][q * 4]) = t;
        }
        __syncthreads();

#pragma unroll
        for (int kss = 0; kss < 4; kss++) {
            const int k = kss * 8;
            wmma::fragment<wmma::matrix_a, 16, 16, 8, wmma::precision::tf32, wmma::row_major> a;
            wmma::load_matrix_sync(a, &As[warp * 16][k], P_LDA);
#pragma unroll
            for (int j = 0; j < 3; j++) {
                wmma::fragment<wmma::matrix_b, 16, 16, 8, wmma::precision::tf32, wmma::col_major> b;
                wmma::load_matrix_sync(b, &Bs[j * 16][k], P_LDA);
                wmma::mma_sync(acc[j], a, b, acc[j]);
            }
        }
        __syncthreads();
    }

#pragma unroll
    for (int j = 0; j < 3; j++)
        wmma::store_matrix_sync(&Zs[warp * 16][j * 16], acc[j], P_LDZ, wmma::mem_row_major);
    __syncthreads();

    for (int idx = tid; idx < P_BM * NPAD; idx += 128) {
        int m = idx / NPAD, col = idx % NPAD;
        g_Zpart[ks][m0 + m][col] = Zs[m][col];
    }
}

// ===========================================================================
// Kernel 3: gating — natural k-order output, raw values
// ===========================================================================
__global__ void gating_kernel() {
    int t = blockIdx.x * blockDim.x + threadIdx.x;
    if (t >= NTOK) return;
    float z[36];
#pragma unroll
    for (int j = 0; j < 9; j++) {
        float4 v = *(const float4*)(&g_Zpart[0][t][j * 4]);
        z[j * 4 + 0] = v.x; z[j * 4 + 1] = v.y; z[j * 4 + 2] = v.z; z[j * 4 + 3] = v.w;
    }
#pragma unroll
    for (int s = 1; s < KSPLIT; s++) {
#pragma unroll
        for (int j = 0; j < 9; j++) {
            float4 v = *(const float4*)(&g_Zpart[s][t][j * 4]);
            z[j * 4 + 0] += v.x; z[j * 4 + 1] += v.y; z[j * 4 + 2] += v.z; z[j * 4 + 3] += v.w;
        }
    }
    float mx = fmaxf(z[0], fmaxf(z[1], z[2]));
    float e0 = expf(z[0] - mx), e1 = expf(z[1] - mx), e2 = expf(z[2] - mx);
    float inv = 1.f / (e0 + e1 + e2);
    float om[3] = {e0 * inv, e1 * inv, e2 * inv};
#pragma unroll
    for (int q = 0; q < CCOLS; q++) {
        float w = (q < 24) ? om[q >> 3] : 1.f;
        g_C[(size_t)t * CCOLS + q] = z[3 + q] * w;
    }
}

// ===========================================================================
// Kernel 4: main GEMM — frozen round-11 config (128x128 tile, 4 warps 2x2,
//   warp tile 64x64, 2 CTAs/SM, 3-stage cp.async). ONLY change: sources are
//   raw x / W (natural k-order; HW tf32 truncation; consistent k-mapping
//   since A and B use the same natural layout + same block selection).
// ===========================================================================
#define BM 128
#define BN 128
#define BKF 32
#define NCHUNK (DIN / BKF)        // 128
#define A_FL (BM * BKF)           // 4096 floats
#define B_FL (BN * BKF)           // 4096 floats
#define STG_FL (A_FL + B_FL)      // 8192 floats
#define A_BYTES (A_FL * 4)        // 16384
#define STG_BYTES (STG_FL * 4)    // 32768
#define SMEM_BYTES (3 * STG_BYTES) // 98304

__device__ __forceinline__ void compute_chunk(
    const float* __restrict__ As, const float* __restrict__ Bs,
    const int* ra0, const int* ra1, const int* rbv,
    const int* off, float acc[4][8][4])
{
#pragma unroll
    for (int j2 = 0; j2 < 2; j2++) {
        uint4 A0[4], A1[4], B[8];
#pragma unroll
        for (int mi = 0; mi < 4; mi++) {
            A0[mi] = *(const uint4*)(As + ra0[mi] + off[j2]);
            A1[mi] = *(const uint4*)(As + ra1[mi] + off[j2]);
        }
#pragma unroll
        for (int nj = 0; nj < 8; nj++)
            B[nj] = *(const uint4*)(Bs + rbv[nj] + off[j2]);

#pragma unroll
        for (int nj = 0; nj < 8; nj++) {
            uint32_t blo[2] = {B[nj].x, B[nj].y};
#pragma unroll
            for (int mi = 0; mi < 4; mi++) {
                uint32_t alo[4] = {A0[mi].x, A1[mi].x, A0[mi].y, A1[mi].y};
                mma_1688(acc[mi][nj], alo, blo);
            }
        }
#pragma unroll
        for (int nj = 0; nj < 8; nj++) {
            uint32_t bhi[2] = {B[nj].z, B[nj].w};
#pragma unroll
            for (int mi = 0; mi < 4; mi++) {
                uint32_t ahi[4] = {A0[mi].z, A1[mi].z, A0[mi].w, A1[mi].w};
                mma_1688(acc[mi][nj], ahi, bhi);
            }
        }
    }
}

__global__ __launch_bounds__(128, 2) void main_mma_kernel(
    const float* __restrict__ x,
    const float* __restrict__ W,
    const float* __restrict__ lora_up,
    float* __restrict__ out)
{
    extern __shared__ float sm[];
    const uint32_t smb = smem_u32(sm);

    const int tid  = threadIdx.x;
    const int warp = tid >> 5;
    const int lane = tid & 31;
    const int qid  = lane >> 2;
    const int tid4 = lane & 3;
    const int wm   = warp >> 1;   // 0..1
    const int wn   = warp & 1;    // 0..1
    const int m0   = blockIdx.y * BM;
    const int n0   = blockIdx.x * BN;

    int ra0[4], ra1[4], rbv[8], off[2];
#pragma unroll
    for (int mi = 0; mi < 4; mi++) {
        int r = wm * 64 + mi * 16 + qid;
        ra0[mi] = r * 32;
        ra1[mi] = ra0[mi] + 8 * 32;
    }
#pragma unroll
    for (int nj = 0; nj < 8; nj++) {
        int r = wn * 64 + nj * 8 + qid;
        rbv[nj] = r * 32;
    }
    const int psw = (qid & 1) << 2;
#pragma unroll
    for (int j2 = 0; j2 < 2; j2++) off[j2] = ((4 * j2 + tid4) ^ psw) << 2;

    const int r0  = tid >> 3;     // 0..15
    const int blk = tid & 7;
    const uint32_t aD = (uint32_t)((r0 * 32 + ((blk ^ ((r0 & 1) << 2)) << 2)) * 4);
    const float* aS = x + (size_t)(m0 + r0) * DIN + blk * 4;
    const float* bS = W + (size_t)(n0 + r0) * DIN + blk * 4;

    float acc[4][8][4];
#pragma unroll
    for (int mi = 0; mi < 4; mi++)
#pragma unroll
        for (int nj = 0; nj < 8; nj++)
#pragma unroll
            for (int e = 0; e < 4; e++) acc[mi][nj][e] = 0.f;

#pragma unroll
    for (int p = 0; p < 2; p++) {
        const uint32_t ab = smb + p * STG_BYTES;
#pragma unroll
        for (int v = 0; v < 8; v++) cp16(ab + aD + v * 2048, aS + (size_t)v * 16 * DIN + p * 32);
#pragma unroll
        for (int v = 0; v < 8; v++) cp16(ab + A_BYTES + aD + v * 2048, bS + (size_t)v * 16 * DIN + p * 32);
        asm volatile("cp.async.commit_group;" ::: "memory");
    }

    int stage = 0;
#pragma unroll 1
    for (int c = 0; c < NCHUNK; c++) {
        if (c == NCHUNK - 1) asm volatile("cp.async.wait_group 0;" ::: "memory");
        else                 asm volatile("cp.async.wait_group 1;" ::: "memory");
        __syncthreads();

        if (c + 2 < NCHUNK) {
            int ns = stage + 2; if (ns >= 3) ns -= 3;
            const uint32_t ab = smb + ns * STG_BYTES;
            const int ko = (c + 2) * 32;
#pragma unroll
            for (int v = 0; v < 8; v++) cp16(ab + aD + v * 2048, aS + (size_t)v * 16 * DIN + ko);
#pragma unroll
            for (int v = 0; v < 8; v++) cp16(ab + A_BYTES + aD + v * 2048, bS + (size_t)v * 16 * DIN + ko);
            asm volatile("cp.async.commit_group;" ::: "memory");
        }

        compute_chunk(sm + stage * STG_FL, sm + stage * STG_FL + A_FL,
                      ra0, ra1, rbv, off, acc);

        stage++; if (stage == 3) stage = 0;
    }

    // ---- LoRA delta chunk: A = gated C (natural order), B = U^T (natural)
    __syncthreads();
    {
#pragma unroll
        for (int v = 0; v < 8; v++) {
            float4 t = *(const float4*)(g_C + (size_t)(m0 + r0 + v * 16) * CCOLS + blk * 4);
            *(float4*)((char*)sm + aD + v * 2048) = t;
        }
        const int n = tid;
        const int nsw = (n & 1) << 2;
#pragma unroll
        for (int k = 0; k < 32; k++) {
            sm[A_FL + n * 32 + (((k >> 2) ^ nsw) << 2) + (k & 3)] =
                lora_up[(size_t)k * DOUT + n0 + n];
        }
    }
    __syncthreads();
    compute_chunk(sm, sm + A_FL, ra0, ra1, rbv, off, acc);

    // ---- epilogue
#pragma unroll
    for (int mi = 0; mi < 4; mi++) {
        const int row = m0 + wm * 64 + mi * 16 + qid;
#pragma unroll
        for (int nj = 0; nj < 8; nj++) {
            const int col = n0 + wn * 64 + nj * 8 + tid4 * 2;
            float2 v0 = make_float2(acc[mi][nj][0], acc[mi][nj][1]);
            float2 v1 = make_float2(acc[mi][nj][2], acc[mi][nj][3]);
            *(float2*)(out + (size_t)row * DOUT + col) = v0;
            *(float2*)(out + (size_t)(row + 8) * DOUT + col) = v1;
        }
    }
}

// ===========================================================================
// Launch: 4 launches, single stream; main GEMM in slot 4 (profiled).
// ===========================================================================
extern "C" void kernel_launch(void* const* d_in, const int* in_sizes, int n_in,
                              void* d_out, int out_size) {
    const float* x          = (const float*)d_in[0];
    const float* W          = (const float*)d_in[1];
    const float* lora_down  = (const float*)d_in[2];
    const float* lora_up    = (const float*)d_in[3];
    const float* lora_route = (const float*)d_in[4];
    float* out = (float*)d_out;

    cudaFuncSetAttribute(main_mma_kernel, cudaFuncAttributeMaxDynamicSharedMemorySize,
                         SMEM_BYTES);

    pack_mt_kernel<<<(NPAD * DIN + 255) / 256, 256>>>(lora_down, lora_route);
    {
        dim3 pgrid(NTOK / P_BM, KSPLIT);   // (128, 8)
        prep_split_kernel<<<pgrid, 128>>>(x);
    }
    gating_kernel<<<NTOK / 256, 256>>>();
    {
        dim3 grid(DOUT / BN, NTOK / BM);   // (32, 64)
        main_mma_kernel<<<grid, 128, SMEM_BYTES>>>(x, W, lora_up, out);
    }
}